// round 1
// baseline (speedup 1.0000x reference)
#include <cuda_runtime.h>
#include <math.h>
#include <stdint.h>

// Problem constants
#define BB 2
#define NN 2048
#define MM 2048
#define DD 1024
#define HH 16
#define HD 64
#define SCALE 0.125f   // 1/sqrt(64)

// ---------------------------------------------------------------------------
// Scratch (allocation-free rule: __device__ globals)
// ---------------------------------------------------------------------------
__device__ float g_Q[(size_t)BB * NN * DD];          // 16 MB
__device__ float g_K[(size_t)BB * MM * DD];          // 16 MB
__device__ float g_V[(size_t)BB * MM * DD];          // 16 MB
__device__ float g_O[(size_t)BB * NN * DD];          // 16 MB
__device__ float g_S[(size_t)BB * HH * NN * MM];     // 512 MB (S, then P in place)

// ---------------------------------------------------------------------------
// GEMM: C[Mrows,1024] = A[Mrows,1024] @ W[1024,1024]^T + bias
// Optional: zero padded key rows (pad != nullptr): row (b,m) zeroed if
// m >= 2048 - pad[b]   (b = gm>>11, m = gm&2047)
// Tiling: 128x128 block, BK=16, 256 threads, 8x8 per thread.
// ---------------------------------------------------------------------------
__global__ __launch_bounds__(256) void gemm_proj(
    const float* __restrict__ A, const float* __restrict__ W,
    const float* __restrict__ bias, float* __restrict__ C,
    const int* __restrict__ pad)
{
    __shared__ float As[16][132];   // [k][m], padded
    __shared__ float Ws[16][132];   // [k][n]

    const int tid = threadIdx.x;
    const int tx = tid & 15, ty = tid >> 4;
    const int m0 = blockIdx.x * 128;
    const int n0 = blockIdx.y * 128;

    float acc[8][8];
#pragma unroll
    for (int i = 0; i < 8; i++)
#pragma unroll
        for (int j = 0; j < 8; j++) acc[i][j] = 0.f;

    for (int k0 = 0; k0 < 1024; k0 += 16) {
#pragma unroll
        for (int it = 0; it < 2; it++) {
            int idx = tid + it * 256;            // 0..511
            int r  = idx >> 2;                   // 0..127
            int c4 = (idx & 3) * 4;              // 0,4,8,12
            float4 va = *(const float4*)&A[(size_t)(m0 + r) * 1024 + k0 + c4];
            As[c4 + 0][r] = va.x; As[c4 + 1][r] = va.y;
            As[c4 + 2][r] = va.z; As[c4 + 3][r] = va.w;
            float4 vw = *(const float4*)&W[(size_t)(n0 + r) * 1024 + k0 + c4];
            Ws[c4 + 0][r] = vw.x; Ws[c4 + 1][r] = vw.y;
            Ws[c4 + 2][r] = vw.z; Ws[c4 + 3][r] = vw.w;
        }
        __syncthreads();
#pragma unroll
        for (int k = 0; k < 16; k++) {
            float a[8], b[8];
            *(float4*)&a[0] = *(const float4*)&As[k][ty * 8];
            *(float4*)&a[4] = *(const float4*)&As[k][ty * 8 + 4];
            *(float4*)&b[0] = *(const float4*)&Ws[k][tx * 8];
            *(float4*)&b[4] = *(const float4*)&Ws[k][tx * 8 + 4];
#pragma unroll
            for (int i = 0; i < 8; i++)
#pragma unroll
                for (int j = 0; j < 8; j++) acc[i][j] += a[i] * b[j];
        }
        __syncthreads();
    }

    float bj[8];
#pragma unroll
    for (int j = 0; j < 8; j++) bj[j] = bias[n0 + tx * 8 + j];

#pragma unroll
    for (int i = 0; i < 8; i++) {
        int gm = m0 + ty * 8 + i;
        bool zr = false;
        if (pad != nullptr) {
            int b  = gm >> 11;
            int ml = gm & 2047;
            zr = (ml >= MM - pad[b]);
        }
        float4 o0, o1;
        if (zr) {
            o0 = make_float4(0.f, 0.f, 0.f, 0.f);
            o1 = o0;
        } else {
            o0 = make_float4(acc[i][0] + bj[0], acc[i][1] + bj[1],
                             acc[i][2] + bj[2], acc[i][3] + bj[3]);
            o1 = make_float4(acc[i][4] + bj[4], acc[i][5] + bj[5],
                             acc[i][6] + bj[6], acc[i][7] + bj[7]);
        }
        float* cp = &C[(size_t)gm * 1024 + n0 + tx * 8];
        *(float4*)&cp[0] = o0;
        *(float4*)&cp[4] = o1;
    }
}

// ---------------------------------------------------------------------------
// Scores: S[bh,n,m] = (Q[b,n,h,:]·K[b,m,h,:]) * SCALE
// 64x64 tiles, K=64 fully resident. Causal: skip tiles with mt > nt.
// ---------------------------------------------------------------------------
__global__ __launch_bounds__(256) void attn_scores(const int* __restrict__ flag)
{
    const int mt = blockIdx.x, nt = blockIdx.y, bh = blockIdx.z;
    const int causal = (flag[0] != 0);
    if (causal && mt > nt) return;

    __shared__ float Qs[64][68];   // [k][n]
    __shared__ float Ks[64][68];   // [k][m]

    const int b = bh >> 4, h = bh & 15;
    const int n0 = nt * 64, m0 = mt * 64;
    const int tid = threadIdx.x;

    const float* Qbase = g_Q + (size_t)b * NN * DD + h * HD;
    const float* Kbase = g_K + (size_t)b * MM * DD + h * HD;

#pragma unroll
    for (int it = 0; it < 4; it++) {
        int idx = tid + it * 256;           // 0..1023
        int r  = idx >> 4;                  // 0..63
        int c4 = (idx & 15) * 4;            // 0..60
        float4 vq = *(const float4*)&Qbase[(size_t)(n0 + r) * DD + c4];
        Qs[c4 + 0][r] = vq.x; Qs[c4 + 1][r] = vq.y;
        Qs[c4 + 2][r] = vq.z; Qs[c4 + 3][r] = vq.w;
        float4 vk = *(const float4*)&Kbase[(size_t)(m0 + r) * DD + c4];
        Ks[c4 + 0][r] = vk.x; Ks[c4 + 1][r] = vk.y;
        Ks[c4 + 2][r] = vk.z; Ks[c4 + 3][r] = vk.w;
    }
    __syncthreads();

    const int tx = tid & 15, ty = tid >> 4;
    float acc[4][4];
#pragma unroll
    for (int i = 0; i < 4; i++)
#pragma unroll
        for (int j = 0; j < 4; j++) acc[i][j] = 0.f;

#pragma unroll 8
    for (int k = 0; k < 64; k++) {
        float a[4], c[4];
        *(float4*)a = *(const float4*)&Qs[k][ty * 4];
        *(float4*)c = *(const float4*)&Ks[k][tx * 4];
#pragma unroll
        for (int i = 0; i < 4; i++)
#pragma unroll
            for (int j = 0; j < 4; j++) acc[i][j] += a[i] * c[j];
    }

#pragma unroll
    for (int i = 0; i < 4; i++) {
        float4 o = make_float4(acc[i][0] * SCALE, acc[i][1] * SCALE,
                               acc[i][2] * SCALE, acc[i][3] * SCALE);
        float* sp = g_S + ((size_t)bh * NN + (n0 + ty * 4 + i)) * MM + m0 + tx * 4;
        *(float4*)sp = o;
    }
}

// ---------------------------------------------------------------------------
// Softmax per row (in place S -> P).
// Causal: only j <= n is valid; -1e6-masked entries underflow to exactly 0 in
// the reference, so we skip them and zero-fill up to the next 64 boundary
// (the region the OV kernel's full-tile loop reads).
// ---------------------------------------------------------------------------
__global__ __launch_bounds__(256) void attn_softmax(const int* __restrict__ flag)
{
    const int blk = blockIdx.x;            // bh*NN + n
    const int n   = blk & (NN - 1);
    const int causal = (flag[0] != 0);
    const int len    = causal ? (n + 1) : MM;
    const int lenpad = causal ? min((((n >> 6) + 1) << 6), MM) : MM;

    float* row = g_S + (size_t)blk * MM;
    const int tid = threadIdx.x;

    float vals[8];
    int cnt = 0;
    float mx = -3.4e38f;
    for (int j = tid; j < len; j += 256) {
        float s = row[j];
        vals[cnt++] = s;
        mx = fmaxf(mx, s);
    }

    __shared__ float red[8];
#pragma unroll
    for (int o = 16; o > 0; o >>= 1) mx = fmaxf(mx, __shfl_xor_sync(0xffffffffu, mx, o));
    if ((tid & 31) == 0) red[tid >> 5] = mx;
    __syncthreads();
    float bm = red[0];
#pragma unroll
    for (int w = 1; w < 8; w++) bm = fmaxf(bm, red[w]);
    __syncthreads();

    float sum = 0.f;
    for (int i = 0; i < cnt; i++) {
        vals[i] = expf(vals[i] - bm);
        sum += vals[i];
    }
#pragma unroll
    for (int o = 16; o > 0; o >>= 1) sum += __shfl_xor_sync(0xffffffffu, sum, o);
    if ((tid & 31) == 0) red[tid >> 5] = sum;
    __syncthreads();
    float tot = red[0];
#pragma unroll
    for (int w = 1; w < 8; w++) tot += red[w];
    float inv = 1.0f / tot;

    int idx = 0;
    for (int j = tid; j < lenpad; j += 256) {
        float v = (j < len) ? vals[idx++] * inv : 0.f;
        row[j] = v;
    }
}

// ---------------------------------------------------------------------------
// O[b,n,h,:] = sum_j P[bh,n,j] * V[b,j,h,:]
// Block: 64 query rows x 64 head dims for one (nt, bh). j-tiles of 16.
// Causal: only j-tiles up to the diagonal block.
// ---------------------------------------------------------------------------
__global__ __launch_bounds__(256) void attn_ov(const int* __restrict__ flag)
{
    const int nt = blockIdx.x, bh = blockIdx.y;
    const int b = bh >> 4, h = bh & 15;
    const int causal = (flag[0] != 0);
    const int n0 = nt * 64;
    const int jtmax = causal ? ((n0 + 64) >> 4) : (MM >> 4);

    __shared__ float Ps[64][20];   // [n][j], padded
    __shared__ float Vs[16][64];   // [j][d]

    const int tid = threadIdx.x;
    const int tx = tid & 15, ty = tid >> 4;
    const int lr = tid >> 2, lc = (tid & 3) * 4;     // P loader
    const int vr = tid >> 4, vc = (tid & 15) * 4;    // V loader

    const float* Pbase = g_S + ((size_t)bh * NN + n0) * MM;
    const float* Vbase = g_V + (size_t)b * MM * DD + h * HD;

    float acc[4][4];
#pragma unroll
    for (int i = 0; i < 4; i++)
#pragma unroll
        for (int j = 0; j < 4; j++) acc[i][j] = 0.f;

    for (int jt = 0; jt < jtmax; jt++) {
        const int j0 = jt * 16;
        float4 vp = *(const float4*)&Pbase[(size_t)lr * MM + j0 + lc];
        *(float4*)&Ps[lr][lc] = vp;
        float4 vv = *(const float4*)&Vbase[(size_t)(j0 + vr) * DD + vc];
        *(float4*)&Vs[vr][vc] = vv;
        __syncthreads();
#pragma unroll
        for (int j = 0; j < 16; j++) {
            float a[4];
#pragma unroll
            for (int i = 0; i < 4; i++) a[i] = Ps[ty * 4 + i][j];
            float4 vb = *(const float4*)&Vs[j][tx * 4];
#pragma unroll
            for (int i = 0; i < 4; i++) {
                acc[i][0] += a[i] * vb.x;
                acc[i][1] += a[i] * vb.y;
                acc[i][2] += a[i] * vb.z;
                acc[i][3] += a[i] * vb.w;
            }
        }
        __syncthreads();
    }

#pragma unroll
    for (int i = 0; i < 4; i++) {
        float* op = g_O + ((size_t)b * NN + n0 + ty * 4 + i) * DD + h * HD + tx * 4;
        *(float4*)op = make_float4(acc[i][0], acc[i][1], acc[i][2], acc[i][3]);
    }
}

// ---------------------------------------------------------------------------
// wmean[b,n,j] = mean_h P[b,h,n,j]; 0 above the causal diagonal.
// ---------------------------------------------------------------------------
__global__ __launch_bounds__(256) void attn_wmean(const int* __restrict__ flag,
                                                  float* __restrict__ wout)
{
    const int blk = blockIdx.x;            // b*NN + n
    const int b = blk >> 11, n = blk & (NN - 1);
    const int causal = (flag[0] != 0);

    const float* base = g_S + ((size_t)(b * HH) * NN + n) * MM;
    float* orow = wout + (size_t)blk * MM;

    for (int j = threadIdx.x; j < MM; j += 256) {
        float acc = 0.f;
        if (!causal || j <= n) {
#pragma unroll
            for (int h = 0; h < HH; h++)
                acc += base[(size_t)h * NN * MM + j];
            acc *= (1.0f / HH);
        }
        orow[j] = acc;
    }
}

// ---------------------------------------------------------------------------
// Launch
// metadata order: query, key, value, key_padding_len, is_attn_mask_len,
//                 wq_w, wq_b, wk_w, wk_b, wv_w, wv_b, wo_w, wo_b
// d_out: [out (B*N*D)] then [w.mean (B*N*M)]
// ---------------------------------------------------------------------------
extern "C" void kernel_launch(void* const* d_in, const int* in_sizes, int n_in,
                              void* d_out, int out_size)
{
    const float* query = (const float*)d_in[0];
    const float* key   = (const float*)d_in[1];
    const float* value = (const float*)d_in[2];
    const int*   kpl   = (const int*)d_in[3];
    const int*   flag  = (const int*)d_in[4];
    const float* wq_w  = (const float*)d_in[5];
    const float* wq_b  = (const float*)d_in[6];
    const float* wk_w  = (const float*)d_in[7];
    const float* wk_b  = (const float*)d_in[8];
    const float* wv_w  = (const float*)d_in[9];
    const float* wv_b  = (const float*)d_in[10];
    const float* wo_w  = (const float*)d_in[11];
    const float* wo_b  = (const float*)d_in[12];
    float* out = (float*)d_out;

    float *Qp, *Kp, *Vp, *Op;
    cudaGetSymbolAddress((void**)&Qp, g_Q);
    cudaGetSymbolAddress((void**)&Kp, g_K);
    cudaGetSymbolAddress((void**)&Vp, g_V);
    cudaGetSymbolAddress((void**)&Op, g_O);

    const dim3 gProj(32, 8);   // 4096/128 x 1024/128

    gemm_proj<<<gProj, 256>>>(query, wq_w, wq_b, Qp, nullptr);
    gemm_proj<<<gProj, 256>>>(key,   wk_w, wk_b, Kp, kpl);
    gemm_proj<<<gProj, 256>>>(value, wv_w, wv_b, Vp, nullptr);

    attn_scores <<<dim3(32, 32, 32), 256>>>(flag);
    attn_softmax<<<BB * HH * NN, 256>>>(flag);
    attn_ov     <<<dim3(32, 32), 256>>>(flag);

    gemm_proj<<<gProj, 256>>>(Op, wo_w, wo_b, out, nullptr);

    const long long need = (long long)BB * NN * DD + (long long)BB * NN * MM;
    if ((long long)out_size >= need)
        attn_wmean<<<BB * NN, 256>>>(flag, out + (size_t)BB * NN * DD);
}

// round 2
// speedup vs baseline: 1.1733x; 1.1733x over previous
#include <cuda_runtime.h>
#include <math.h>
#include <stdint.h>

// Problem constants
#define BB 2
#define NN 2048
#define MM 2048
#define DD 1024
#define HH 16
#define HD 64
#define SCALE 0.125f   // 1/sqrt(64)

#define SROW 20        // smem row stride (floats) for 16-wide k tile + pad

// ---------------------------------------------------------------------------
// Scratch (allocation-free rule: __device__ globals)
// ---------------------------------------------------------------------------
__device__ float g_Q[(size_t)BB * NN * DD];          // 16 MB
__device__ float g_K[(size_t)BB * MM * DD];          // 16 MB
__device__ float g_V[(size_t)BB * MM * DD];          // 16 MB
__device__ float g_O[(size_t)BB * NN * DD];          // 16 MB
__device__ float g_S[(size_t)BB * HH * NN * MM];     // 512 MB (S, then P in place)

// ---------------------------------------------------------------------------
// TF32 helpers
// ---------------------------------------------------------------------------
__device__ __forceinline__ void split_tf32(float x, uint32_t& hi, uint32_t& lo) {
    asm("cvt.rna.tf32.f32 %0, %1;" : "=r"(hi) : "f"(x));
    float l = x - __uint_as_float(hi);
    asm("cvt.rna.tf32.f32 %0, %1;" : "=r"(lo) : "f"(l));
}

#define MMA_TF32(d, a0, a1, a2, a3, b0, b1)                               \
    asm volatile("mma.sync.aligned.m16n8k8.row.col.f32.tf32.tf32.f32 "    \
        "{%0,%1,%2,%3}, {%4,%5,%6,%7}, {%8,%9}, {%0,%1,%2,%3};"           \
        : "+f"(d[0]), "+f"(d[1]), "+f"(d[2]), "+f"(d[3])                  \
        : "r"(a0), "r"(a1), "r"(a2), "r"(a3), "r"(b0), "r"(b1))

__device__ __forceinline__ void cp16(uint32_t dst, const void* src) {
    asm volatile("cp.async.ca.shared.global [%0], [%1], 16;" :: "r"(dst), "l"(src));
}
__device__ __forceinline__ void cp_commit() {
    asm volatile("cp.async.commit_group;");
}
__device__ __forceinline__ void cp_wait1() {
    asm volatile("cp.async.wait_group 1;");
}
__device__ __forceinline__ void cp_wait0() {
    asm volatile("cp.async.wait_group 0;");
}

// Load one 128x16 tile (A rows) into smem buffer [128][SROW].
// Each thread copies chunks tid and tid+256: chunk c -> row=c>>2, kc=(c&3)*4.
__device__ __forceinline__ void load_tile16(uint32_t s_base, const float* gsrc,
                                            int ld, int k0, int tid) {
    int c0 = tid;
    int r0 = c0 >> 2, kc0 = (c0 & 3) * 4;
    cp16(s_base + (uint32_t)(r0 * SROW + kc0) * 4, gsrc + (size_t)r0 * ld + k0 + kc0);
    int c1 = tid + 256;
    int r1 = c1 >> 2, kc1 = (c1 & 3) * 4;
    cp16(s_base + (uint32_t)(r1 * SROW + kc1) * 4, gsrc + (size_t)r1 * ld + k0 + kc1);
}

// Shared 3xTF32 mainloop: acc[mt][nt][4] += Ablk(128xK) * Bblk(128xK)^T
// sa/sb: [2][128][SROW] double buffers. Warp tile 64x32 (2x4 warp grid).
__device__ __forceinline__ void mma3_mainloop(
    const float* __restrict__ Ab, int lda,
    const float* __restrict__ Bb, int ldb, int ktiles,
    float (&sa)[2][128][SROW], float (&sb)[2][128][SROW],
    float (&acc)[4][4][4], int tid)
{
    const int lane = tid & 31;
    const int warp = tid >> 5;
    const int g = lane >> 2, t = lane & 3;
    const int wm0 = (warp >> 2) * 64;
    const int wn0 = (warp & 3) * 32;

    uint32_t sA = (uint32_t)__cvta_generic_to_shared(&sa[0][0][0]);
    uint32_t sB = (uint32_t)__cvta_generic_to_shared(&sb[0][0][0]);
    const uint32_t bufbytes = 128 * SROW * 4;

    // preload tile 0 into buf 0
    load_tile16(sA, Ab, lda, 0, tid);
    load_tile16(sB, Bb, ldb, 0, tid);
    cp_commit();

    for (int tl = 0; tl < ktiles; tl++) {
        const int buf = tl & 1;
        if (tl + 1 < ktiles) {
            uint32_t off = (buf ^ 1) * bufbytes;
            load_tile16(sA + off, Ab, lda, (tl + 1) * 16, tid);
            load_tile16(sB + off, Bb, ldb, (tl + 1) * 16, tid);
            cp_commit();
            cp_wait1();
        } else {
            cp_wait0();
        }
        __syncthreads();

#pragma unroll
        for (int ks = 0; ks < 2; ks++) {
            const int k0 = ks * 8 + t;
            uint32_t ah[4][4], al[4][4];
#pragma unroll
            for (int mt = 0; mt < 4; mt++) {
                int r = wm0 + mt * 16 + g;
                split_tf32(sa[buf][r][k0],         ah[mt][0], al[mt][0]);
                split_tf32(sa[buf][r + 8][k0],     ah[mt][1], al[mt][1]);
                split_tf32(sa[buf][r][k0 + 4],     ah[mt][2], al[mt][2]);
                split_tf32(sa[buf][r + 8][k0 + 4], ah[mt][3], al[mt][3]);
            }
#pragma unroll
            for (int nt = 0; nt < 4; nt++) {
                int c = wn0 + nt * 8 + g;
                uint32_t bh0, bl0, bh1, bl1;
                split_tf32(sb[buf][c][k0],     bh0, bl0);
                split_tf32(sb[buf][c][k0 + 4], bh1, bl1);
#pragma unroll
                for (int mt = 0; mt < 4; mt++) {
                    float* d = acc[mt][nt];
                    MMA_TF32(d, ah[mt][0], ah[mt][1], ah[mt][2], ah[mt][3], bh0, bh1);
                    MMA_TF32(d, ah[mt][0], ah[mt][1], ah[mt][2], ah[mt][3], bl0, bl1);
                    MMA_TF32(d, al[mt][0], al[mt][1], al[mt][2], al[mt][3], bh0, bh1);
                }
            }
        }
        __syncthreads();
    }
}

// ---------------------------------------------------------------------------
// Projection GEMM: C[4096,1024] = A[4096,1024] @ W[1024,1024]^T + bias
// Optional padded-key-row zeroing (pad != nullptr).
// Grid (32, 8), block 256.
// ---------------------------------------------------------------------------
__global__ __launch_bounds__(256, 2) void proj_mma(
    const float* __restrict__ A, const float* __restrict__ W,
    const float* __restrict__ bias, float* __restrict__ C,
    const int* __restrict__ pad)
{
    __shared__ float sa[2][128][SROW];
    __shared__ float sb[2][128][SROW];

    const int tid = threadIdx.x;
    const int m0 = blockIdx.x * 128;
    const int n0 = blockIdx.y * 128;

    float acc[4][4][4];
#pragma unroll
    for (int i = 0; i < 4; i++)
#pragma unroll
        for (int j = 0; j < 4; j++)
#pragma unroll
            for (int q = 0; q < 4; q++) acc[i][j][q] = 0.f;

    mma3_mainloop(A + (size_t)m0 * 1024, 1024,
                  W + (size_t)n0 * 1024, 1024, 64, sa, sb, acc, tid);

    const int lane = tid & 31;
    const int warp = tid >> 5;
    const int g = lane >> 2, t = lane & 3;
    const int wm0 = (warp >> 2) * 64;
    const int wn0 = (warp & 3) * 32;

#pragma unroll
    for (int mt = 0; mt < 4; mt++) {
        int r0 = m0 + wm0 + mt * 16 + g;
        int r1 = r0 + 8;
        bool z0 = false, z1 = false;
        if (pad != nullptr) {
            z0 = ((r0 & 2047) >= MM - pad[r0 >> 11]);
            z1 = ((r1 & 2047) >= MM - pad[r1 >> 11]);
        }
#pragma unroll
        for (int nt = 0; nt < 4; nt++) {
            int col = n0 + wn0 + nt * 8 + 2 * t;
            float2 bi = *(const float2*)&bias[col];
            float* d = acc[mt][nt];
            float2 o0 = z0 ? make_float2(0.f, 0.f)
                           : make_float2(d[0] + bi.x, d[1] + bi.y);
            float2 o1 = z1 ? make_float2(0.f, 0.f)
                           : make_float2(d[2] + bi.x, d[3] + bi.y);
            *(float2*)&C[(size_t)r0 * 1024 + col] = o0;
            *(float2*)&C[(size_t)r1 * 1024 + col] = o1;
        }
    }
}

// ---------------------------------------------------------------------------
// Scores: S[bh,n,m] = (Q[b,n,h,:]·K[b,m,h,:]) * SCALE, 128x128 tiles, K=64.
// Causal: skip tiles fully above the diagonal.
// Grid (mt=16, nt=16, bh=32), block 256.
// ---------------------------------------------------------------------------
__global__ __launch_bounds__(256, 2) void scores_mma(const int* __restrict__ flag)
{
    const int mt = blockIdx.x, ntb = blockIdx.y, bh = blockIdx.z;
    if (flag[0] != 0 && mt > ntb) return;

    __shared__ float sa[2][128][SROW];
    __shared__ float sb[2][128][SROW];

    const int b = bh >> 4, h = bh & 15;
    const int n0 = ntb * 128, m0 = mt * 128;
    const int tid = threadIdx.x;

    float acc[4][4][4];
#pragma unroll
    for (int i = 0; i < 4; i++)
#pragma unroll
        for (int j = 0; j < 4; j++)
#pragma unroll
            for (int q = 0; q < 4; q++) acc[i][j][q] = 0.f;

    const float* Ab = g_Q + (size_t)b * NN * DD + (size_t)n0 * DD + h * HD;
    const float* Bb = g_K + (size_t)b * MM * DD + (size_t)m0 * DD + h * HD;

    mma3_mainloop(Ab, DD, Bb, DD, 4, sa, sb, acc, tid);

    const int lane = tid & 31;
    const int warp = tid >> 5;
    const int g = lane >> 2, t = lane & 3;
    const int wm0 = (warp >> 2) * 64;   // query-row dir
    const int wn0 = (warp & 3) * 32;    // key-col dir

    float* Sbase = g_S + (size_t)bh * NN * MM;
#pragma unroll
    for (int qt = 0; qt < 4; qt++) {
        int r0 = n0 + wm0 + qt * 16 + g;
        int r1 = r0 + 8;
#pragma unroll
        for (int kt = 0; kt < 4; kt++) {
            int col = m0 + wn0 + kt * 8 + 2 * t;
            float* d = acc[qt][kt];
            *(float2*)&Sbase[(size_t)r0 * MM + col] =
                make_float2(d[0] * SCALE, d[1] * SCALE);
            *(float2*)&Sbase[(size_t)r1 * MM + col] =
                make_float2(d[2] * SCALE, d[3] * SCALE);
        }
    }
}

// ---------------------------------------------------------------------------
// Softmax per row (in place S -> P).
// Causal: only j <= n valid; zero-fill up to the next 128 boundary (the
// region the 128-row OV kernel reads).
// ---------------------------------------------------------------------------
__global__ __launch_bounds__(256) void attn_softmax(const int* __restrict__ flag)
{
    const int blk = blockIdx.x;            // bh*NN + n
    const int n   = blk & (NN - 1);
    const int causal = (flag[0] != 0);
    const int len    = causal ? (n + 1) : MM;
    const int lenpad = causal ? min((((n >> 7) + 1) << 7), MM) : MM;

    float* row = g_S + (size_t)blk * MM;
    const int tid = threadIdx.x;

    float vals[8];
    int cnt = 0;
    float mx = -3.4e38f;
    for (int j = tid; j < len; j += 256) {
        float s = row[j];
        vals[cnt++] = s;
        mx = fmaxf(mx, s);
    }

    __shared__ float red[8];
#pragma unroll
    for (int o = 16; o > 0; o >>= 1) mx = fmaxf(mx, __shfl_xor_sync(0xffffffffu, mx, o));
    if ((tid & 31) == 0) red[tid >> 5] = mx;
    __syncthreads();
    float bm = red[0];
#pragma unroll
    for (int w = 1; w < 8; w++) bm = fmaxf(bm, red[w]);
    __syncthreads();

    float sum = 0.f;
    for (int i = 0; i < cnt; i++) {
        vals[i] = expf(vals[i] - bm);
        sum += vals[i];
    }
#pragma unroll
    for (int o = 16; o > 0; o >>= 1) sum += __shfl_xor_sync(0xffffffffu, sum, o);
    if ((tid & 31) == 0) red[tid >> 5] = sum;
    __syncthreads();
    float tot = red[0];
#pragma unroll
    for (int w = 1; w < 8; w++) tot += red[w];
    float inv = 1.0f / tot;

    int idx = 0;
    for (int j = tid; j < lenpad; j += 256) {
        float v = (j < len) ? vals[idx++] * inv : 0.f;
        row[j] = v;
    }
}

// ---------------------------------------------------------------------------
// O[b,n,h,:] = sum_j P[bh,n,j] * V[b,j,h,:]
// Block: 128 query rows x 64 head dims for one (nt, bh). j-tiles of 16.
// Thread tile 8(n) x 4(d). Causal: j-tiles up to n0+128 (zero-padded by softmax).
// ---------------------------------------------------------------------------
__global__ __launch_bounds__(256) void attn_ov(const int* __restrict__ flag)
{
    const int ntb = blockIdx.x, bh = blockIdx.y;
    const int b = bh >> 4, h = bh & 15;
    const int n0 = ntb * 128;
    const int jtmax = (flag[0] != 0) ? ((n0 + 128) >> 4) : (MM >> 4);

    __shared__ float Ps[16][132];   // [j][n], padded
    __shared__ float Vs[16][68];    // [j][d]

    const int tid = threadIdx.x;
    const int tx = tid & 15, ty = tid >> 4;
    const int vr = tid >> 4, vc = (tid & 15) * 4;    // V loader

    const float* Pbase = g_S + ((size_t)bh * NN + n0) * MM;
    const float* Vbase = g_V + (size_t)b * MM * DD + h * HD;

    float acc[8][4];
#pragma unroll
    for (int i = 0; i < 8; i++)
#pragma unroll
        for (int q = 0; q < 4; q++) acc[i][q] = 0.f;

    for (int jt = 0; jt < jtmax; jt++) {
        const int j0 = jt * 16;
        // P: 128 rows x 16 j -> transposed smem [j][n]
#pragma unroll
        for (int it = 0; it < 2; it++) {
            int c = tid + it * 256;          // 0..511
            int r = c >> 2, jc = (c & 3) * 4;
            float4 vp = *(const float4*)&Pbase[(size_t)r * MM + j0 + jc];
            Ps[jc + 0][r] = vp.x; Ps[jc + 1][r] = vp.y;
            Ps[jc + 2][r] = vp.z; Ps[jc + 3][r] = vp.w;
        }
        float4 vv = *(const float4*)&Vbase[(size_t)(j0 + vr) * DD + vc];
        *(float4*)&Vs[vr][vc] = vv;
        __syncthreads();
#pragma unroll
        for (int j = 0; j < 16; j++) {
            float4 v = *(const float4*)&Vs[j][tx * 4];
#pragma unroll
            for (int i = 0; i < 8; i++) {
                float a = Ps[j][ty * 8 + i];
                acc[i][0] += a * v.x;
                acc[i][1] += a * v.y;
                acc[i][2] += a * v.z;
                acc[i][3] += a * v.w;
            }
        }
        __syncthreads();
    }

#pragma unroll
    for (int i = 0; i < 8; i++) {
        float* op = g_O + ((size_t)b * NN + n0 + ty * 8 + i) * DD + h * HD + tx * 4;
        *(float4*)op = make_float4(acc[i][0], acc[i][1], acc[i][2], acc[i][3]);
    }
}

// ---------------------------------------------------------------------------
// wmean[b,n,j] = mean_h P[b,h,n,j]; 0 above the causal diagonal. float4.
// ---------------------------------------------------------------------------
__global__ __launch_bounds__(256) void attn_wmean(const int* __restrict__ flag,
                                                  float* __restrict__ wout)
{
    const int blk = blockIdx.x;            // b*NN + n
    const int b = blk >> 11, n = blk & (NN - 1);
    const int causal = (flag[0] != 0);

    const float* base = g_S + ((size_t)(b * HH) * NN + n) * MM;
    float* orow = wout + (size_t)blk * MM;

    for (int j4 = threadIdx.x * 4; j4 < MM; j4 += 1024) {
        float4 a = make_float4(0.f, 0.f, 0.f, 0.f);
        if (!causal || j4 <= n) {
#pragma unroll
            for (int h = 0; h < HH; h++) {
                float4 v = *(const float4*)&base[(size_t)h * NN * MM + j4];
                a.x += v.x; a.y += v.y; a.z += v.z; a.w += v.w;
            }
            a.x *= (1.0f / HH); a.y *= (1.0f / HH);
            a.z *= (1.0f / HH); a.w *= (1.0f / HH);
            if (causal) {
                if (j4 + 1 > n) a.y = 0.f;
                if (j4 + 2 > n) a.z = 0.f;
                if (j4 + 3 > n) a.w = 0.f;
            }
        }
        *(float4*)&orow[j4] = a;
    }
}

// ---------------------------------------------------------------------------
// Launch
// ---------------------------------------------------------------------------
extern "C" void kernel_launch(void* const* d_in, const int* in_sizes, int n_in,
                              void* d_out, int out_size)
{
    const float* query = (const float*)d_in[0];
    const float* key   = (const float*)d_in[1];
    const float* value = (const float*)d_in[2];
    const int*   kpl   = (const int*)d_in[3];
    const int*   flag  = (const int*)d_in[4];
    const float* wq_w  = (const float*)d_in[5];
    const float* wq_b  = (const float*)d_in[6];
    const float* wk_w  = (const float*)d_in[7];
    const float* wk_b  = (const float*)d_in[8];
    const float* wv_w  = (const float*)d_in[9];
    const float* wv_b  = (const float*)d_in[10];
    const float* wo_w  = (const float*)d_in[11];
    const float* wo_b  = (const float*)d_in[12];
    float* out = (float*)d_out;

    float *Qp, *Kp, *Vp, *Op;
    cudaGetSymbolAddress((void**)&Qp, g_Q);
    cudaGetSymbolAddress((void**)&Kp, g_K);
    cudaGetSymbolAddress((void**)&Vp, g_V);
    cudaGetSymbolAddress((void**)&Op, g_O);

    const dim3 gProj(32, 8);   // 4096/128 x 1024/128

    proj_mma<<<gProj, 256>>>(query, wq_w, wq_b, Qp, nullptr);
    proj_mma<<<gProj, 256>>>(key,   wk_w, wk_b, Kp, kpl);
    proj_mma<<<gProj, 256>>>(value, wv_w, wv_b, Vp, nullptr);

    scores_mma  <<<dim3(16, 16, 32), 256>>>(flag);
    attn_softmax<<<BB * HH * NN, 256>>>(flag);
    attn_ov     <<<dim3(16, 32), 256>>>(flag);

    proj_mma<<<gProj, 256>>>(Op, wo_w, wo_b, out, nullptr);

    const long long need = (long long)BB * NN * DD + (long long)BB * NN * MM;
    if ((long long)out_size >= need)
        attn_wmean<<<BB * NN, 256>>>(flag, out + (size_t)BB * NN * DD);
}

// round 3
// speedup vs baseline: 1.5324x; 1.3060x over previous
#include <cuda_runtime.h>
#include <cuda_bf16.h>
#include <math.h>
#include <stdint.h>

// Problem constants
#define BB 2
#define NN 2048
#define MM 2048
#define DD 1024
#define HH 16
#define HD 64
#define SCALE 0.125f   // 1/sqrt(64)

#define SROW 20        // smem row stride (floats) for 16-wide k tile + pad

// ---------------------------------------------------------------------------
// Scratch (allocation-free rule: __device__ globals)
// ---------------------------------------------------------------------------
__device__ float g_Q[(size_t)BB * NN * DD];          // 16 MB
__device__ float g_K[(size_t)BB * MM * DD];          // 16 MB
__device__ float g_V[(size_t)BB * MM * DD];          // 16 MB
__device__ float g_O[(size_t)BB * NN * DD];          // 16 MB
__device__ float g_S[(size_t)BB * HH * NN * MM];     // 512 MB (S, then P in place)

// ---------------------------------------------------------------------------
// bf16 3-term split helpers
// ---------------------------------------------------------------------------
__device__ __forceinline__ void split_bf16x2(float2 v, uint32_t& hi, uint32_t& lo) {
    __nv_bfloat162 h = __float22bfloat162_rn(v);
    float2 hf = __bfloat1622float2(h);
    __nv_bfloat162 l = __float22bfloat162_rn(make_float2(v.x - hf.x, v.y - hf.y));
    hi = *(uint32_t*)&h;
    lo = *(uint32_t*)&l;
}

#define MMA_BF16(d, a0, a1, a2, a3, b0, b1)                                \
    asm volatile("mma.sync.aligned.m16n8k16.row.col.f32.bf16.bf16.f32 "    \
        "{%0,%1,%2,%3}, {%4,%5,%6,%7}, {%8,%9}, {%0,%1,%2,%3};"            \
        : "+f"(d[0]), "+f"(d[1]), "+f"(d[2]), "+f"(d[3])                   \
        : "r"(a0), "r"(a1), "r"(a2), "r"(a3), "r"(b0), "r"(b1))

__device__ __forceinline__ void cp16(uint32_t dst, const void* src) {
    asm volatile("cp.async.ca.shared.global [%0], [%1], 16;" :: "r"(dst), "l"(src));
}
__device__ __forceinline__ void cp_commit() {
    asm volatile("cp.async.commit_group;");
}
__device__ __forceinline__ void cp_wait1() {
    asm volatile("cp.async.wait_group 1;");
}
__device__ __forceinline__ void cp_wait0() {
    asm volatile("cp.async.wait_group 0;");
}

// Load one 128x16 tile (rows of A/B) into smem buffer [128][SROW].
__device__ __forceinline__ void load_tile16(uint32_t s_base, const float* gsrc,
                                            int ld, int k0, int tid) {
    int c0 = tid;
    int r0 = c0 >> 2, kc0 = (c0 & 3) * 4;
    cp16(s_base + (uint32_t)(r0 * SROW + kc0) * 4, gsrc + (size_t)r0 * ld + k0 + kc0);
    int c1 = tid + 256;
    int r1 = c1 >> 2, kc1 = (c1 & 3) * 4;
    cp16(s_base + (uint32_t)(r1 * SROW + kc1) * 4, gsrc + (size_t)r1 * ld + k0 + kc1);
}

// Shared 3-term bf16 mainloop: acc[mt][nt][4] += Ablk(128xK) * Bblk(128xK)^T
// sa/sb: [2][128][SROW] fp32 double buffers. Warp tile 64x32 (2x4 warp grid).
// Per 16-deep k-tile: one m16n8k16 per (mt,nt) per term (3 terms).
__device__ __forceinline__ void mma3_mainloop(
    const float* __restrict__ Ab, int lda,
    const float* __restrict__ Bb, int ldb, int ktiles,
    float (&sa)[2][128][SROW], float (&sb)[2][128][SROW],
    float (&acc)[4][4][4], int tid)
{
    const int lane = tid & 31;
    const int warp = tid >> 5;
    const int g = lane >> 2, t = lane & 3;
    const int wm0 = (warp >> 2) * 64;
    const int wn0 = (warp & 3) * 32;

    uint32_t sA = (uint32_t)__cvta_generic_to_shared(&sa[0][0][0]);
    uint32_t sB = (uint32_t)__cvta_generic_to_shared(&sb[0][0][0]);
    const uint32_t bufbytes = 128 * SROW * 4;

    // preload tile 0 into buf 0
    load_tile16(sA, Ab, lda, 0, tid);
    load_tile16(sB, Bb, ldb, 0, tid);
    cp_commit();

    for (int tl = 0; tl < ktiles; tl++) {
        const int buf = tl & 1;
        if (tl + 1 < ktiles) {
            uint32_t off = (buf ^ 1) * bufbytes;
            load_tile16(sA + off, Ab, lda, (tl + 1) * 16, tid);
            load_tile16(sB + off, Bb, ldb, (tl + 1) * 16, tid);
            cp_commit();
            cp_wait1();
        } else {
            cp_wait0();
        }
        __syncthreads();

        // A fragments for this k-tile (k = 0..15)
        uint32_t ah[4][4], al[4][4];
#pragma unroll
        for (int mt = 0; mt < 4; mt++) {
            int r = wm0 + mt * 16 + g;
            float2 p00 = *(const float2*)&sa[buf][r][2 * t];          // row g,   k 2t,2t+1
            float2 p10 = *(const float2*)&sa[buf][r + 8][2 * t];      // row g+8, k 2t,2t+1
            float2 p01 = *(const float2*)&sa[buf][r][8 + 2 * t];      // row g,   k 8+2t..
            float2 p11 = *(const float2*)&sa[buf][r + 8][8 + 2 * t];  // row g+8, k 8+2t..
            split_bf16x2(p00, ah[mt][0], al[mt][0]);
            split_bf16x2(p10, ah[mt][1], al[mt][1]);
            split_bf16x2(p01, ah[mt][2], al[mt][2]);
            split_bf16x2(p11, ah[mt][3], al[mt][3]);
        }
#pragma unroll
        for (int nt = 0; nt < 4; nt++) {
            int c = wn0 + nt * 8 + g;
            float2 q0 = *(const float2*)&sb[buf][c][2 * t];
            float2 q1 = *(const float2*)&sb[buf][c][8 + 2 * t];
            uint32_t bh0, bl0, bh1, bl1;
            split_bf16x2(q0, bh0, bl0);
            split_bf16x2(q1, bh1, bl1);
#pragma unroll
            for (int mt = 0; mt < 4; mt++) {
                float* d = acc[mt][nt];
                MMA_BF16(d, ah[mt][0], ah[mt][1], ah[mt][2], ah[mt][3], bh0, bh1);
                MMA_BF16(d, ah[mt][0], ah[mt][1], ah[mt][2], ah[mt][3], bl0, bl1);
                MMA_BF16(d, al[mt][0], al[mt][1], al[mt][2], al[mt][3], bh0, bh1);
            }
        }
        __syncthreads();
    }
}

// ---------------------------------------------------------------------------
// Projection GEMM: C[4096,1024] = A[4096,1024] @ W[1024,1024]^T + bias
// Optional padded-key-row zeroing (pad != nullptr).
// Grid (32, 8), block 256.
// ---------------------------------------------------------------------------
__global__ __launch_bounds__(256, 2) void proj_mma(
    const float* __restrict__ A, const float* __restrict__ W,
    const float* __restrict__ bias, float* __restrict__ C,
    const int* __restrict__ pad)
{
    __shared__ float sa[2][128][SROW];
    __shared__ float sb[2][128][SROW];

    const int tid = threadIdx.x;
    const int m0 = blockIdx.x * 128;
    const int n0 = blockIdx.y * 128;

    float acc[4][4][4];
#pragma unroll
    for (int i = 0; i < 4; i++)
#pragma unroll
        for (int j = 0; j < 4; j++)
#pragma unroll
            for (int q = 0; q < 4; q++) acc[i][j][q] = 0.f;

    mma3_mainloop(A + (size_t)m0 * 1024, 1024,
                  W + (size_t)n0 * 1024, 1024, 64, sa, sb, acc, tid);

    const int lane = tid & 31;
    const int warp = tid >> 5;
    const int g = lane >> 2, t = lane & 3;
    const int wm0 = (warp >> 2) * 64;
    const int wn0 = (warp & 3) * 32;

#pragma unroll
    for (int mt = 0; mt < 4; mt++) {
        int r0 = m0 + wm0 + mt * 16 + g;
        int r1 = r0 + 8;
        bool z0 = false, z1 = false;
        if (pad != nullptr) {
            z0 = ((r0 & 2047) >= MM - pad[r0 >> 11]);
            z1 = ((r1 & 2047) >= MM - pad[r1 >> 11]);
        }
#pragma unroll
        for (int nt = 0; nt < 4; nt++) {
            int col = n0 + wn0 + nt * 8 + 2 * t;
            float2 bi = *(const float2*)&bias[col];
            float* d = acc[mt][nt];
            float2 o0 = z0 ? make_float2(0.f, 0.f)
                           : make_float2(d[0] + bi.x, d[1] + bi.y);
            float2 o1 = z1 ? make_float2(0.f, 0.f)
                           : make_float2(d[2] + bi.x, d[3] + bi.y);
            *(float2*)&C[(size_t)r0 * 1024 + col] = o0;
            *(float2*)&C[(size_t)r1 * 1024 + col] = o1;
        }
    }
}

// ---------------------------------------------------------------------------
// Scores: S[bh,n,m] = (Q[b,n,h,:]·K[b,m,h,:]) * SCALE, 128x128 tiles, K=64.
// Causal: skip tiles fully above the diagonal.
// Grid (mt=16, nt=16, bh=32), block 256.
// ---------------------------------------------------------------------------
__global__ __launch_bounds__(256, 2) void scores_mma(const int* __restrict__ flag)
{
    const int mt = blockIdx.x, ntb = blockIdx.y, bh = blockIdx.z;
    if (flag[0] != 0 && mt > ntb) return;

    __shared__ float sa[2][128][SROW];
    __shared__ float sb[2][128][SROW];

    const int b = bh >> 4, h = bh & 15;
    const int n0 = ntb * 128, m0 = mt * 128;
    const int tid = threadIdx.x;

    float acc[4][4][4];
#pragma unroll
    for (int i = 0; i < 4; i++)
#pragma unroll
        for (int j = 0; j < 4; j++)
#pragma unroll
            for (int q = 0; q < 4; q++) acc[i][j][q] = 0.f;

    const float* Ab = g_Q + (size_t)b * NN * DD + (size_t)n0 * DD + h * HD;
    const float* Bb = g_K + (size_t)b * MM * DD + (size_t)m0 * DD + h * HD;

    mma3_mainloop(Ab, DD, Bb, DD, 4, sa, sb, acc, tid);

    const int lane = tid & 31;
    const int warp = tid >> 5;
    const int g = lane >> 2, t = lane & 3;
    const int wm0 = (warp >> 2) * 64;   // query-row dir
    const int wn0 = (warp & 3) * 32;    // key-col dir

    float* Sbase = g_S + (size_t)bh * NN * MM;
#pragma unroll
    for (int qt = 0; qt < 4; qt++) {
        int r0 = n0 + wm0 + qt * 16 + g;
        int r1 = r0 + 8;
#pragma unroll
        for (int kt = 0; kt < 4; kt++) {
            int col = m0 + wn0 + kt * 8 + 2 * t;
            float* d = acc[qt][kt];
            *(float2*)&Sbase[(size_t)r0 * MM + col] =
                make_float2(d[0] * SCALE, d[1] * SCALE);
            *(float2*)&Sbase[(size_t)r1 * MM + col] =
                make_float2(d[2] * SCALE, d[3] * SCALE);
        }
    }
}

// ---------------------------------------------------------------------------
// Softmax per row (in place S -> P).
// Causal: only j <= n valid; zero-fill up to the next 128 boundary (the
// region the 128-row OV kernel reads).
// ---------------------------------------------------------------------------
__global__ __launch_bounds__(256) void attn_softmax(const int* __restrict__ flag)
{
    const int blk = blockIdx.x;            // bh*NN + n
    const int n   = blk & (NN - 1);
    const int causal = (flag[0] != 0);
    const int len    = causal ? (n + 1) : MM;
    const int lenpad = causal ? min((((n >> 7) + 1) << 7), MM) : MM;

    float* row = g_S + (size_t)blk * MM;
    const int tid = threadIdx.x;

    float vals[8];
    int cnt = 0;
    float mx = -3.4e38f;
    for (int j = tid; j < len; j += 256) {
        float s = row[j];
        vals[cnt++] = s;
        mx = fmaxf(mx, s);
    }

    __shared__ float red[8];
#pragma unroll
    for (int o = 16; o > 0; o >>= 1) mx = fmaxf(mx, __shfl_xor_sync(0xffffffffu, mx, o));
    if ((tid & 31) == 0) red[tid >> 5] = mx;
    __syncthreads();
    float bm = red[0];
#pragma unroll
    for (int w = 1; w < 8; w++) bm = fmaxf(bm, red[w]);
    __syncthreads();

    float sum = 0.f;
    for (int i = 0; i < cnt; i++) {
        vals[i] = expf(vals[i] - bm);
        sum += vals[i];
    }
#pragma unroll
    for (int o = 16; o > 0; o >>= 1) sum += __shfl_xor_sync(0xffffffffu, sum, o);
    if ((tid & 31) == 0) red[tid >> 5] = sum;
    __syncthreads();
    float tot = red[0];
#pragma unroll
    for (int w = 1; w < 8; w++) tot += red[w];
    float inv = 1.0f / tot;

    int idx = 0;
    for (int j = tid; j < lenpad; j += 256) {
        float v = (j < len) ? vals[idx++] * inv : 0.f;
        row[j] = v;
    }
}

// ---------------------------------------------------------------------------
// O[b,n,h,:] = sum_j P[bh,n,j] * V[b,j,h,:]
// Block: 128 query rows x 64 head dims for one (nt, bh). j-tiles of 16.
// Thread tile 8(n) x 4(d). Causal: j-tiles up to n0+128 (zero-padded by softmax).
// ---------------------------------------------------------------------------
__global__ __launch_bounds__(256) void attn_ov(const int* __restrict__ flag)
{
    const int ntb = blockIdx.x, bh = blockIdx.y;
    const int b = bh >> 4, h = bh & 15;
    const int n0 = ntb * 128;
    const int jtmax = (flag[0] != 0) ? ((n0 + 128) >> 4) : (MM >> 4);

    __shared__ float Ps[16][132];   // [j][n], padded
    __shared__ float Vs[16][68];    // [j][d]

    const int tid = threadIdx.x;
    const int tx = tid & 15, ty = tid >> 4;
    const int vr = tid >> 4, vc = (tid & 15) * 4;    // V loader

    const float* Pbase = g_S + ((size_t)bh * NN + n0) * MM;
    const float* Vbase = g_V + (size_t)b * MM * DD + h * HD;

    float acc[8][4];
#pragma unroll
    for (int i = 0; i < 8; i++)
#pragma unroll
        for (int q = 0; q < 4; q++) acc[i][q] = 0.f;

    for (int jt = 0; jt < jtmax; jt++) {
        const int j0 = jt * 16;
        // P: 128 rows x 16 j -> transposed smem [j][n]
#pragma unroll
        for (int it = 0; it < 2; it++) {
            int c = tid + it * 256;          // 0..511
            int r = c >> 2, jc = (c & 3) * 4;
            float4 vp = *(const float4*)&Pbase[(size_t)r * MM + j0 + jc];
            Ps[jc + 0][r] = vp.x; Ps[jc + 1][r] = vp.y;
            Ps[jc + 2][r] = vp.z; Ps[jc + 3][r] = vp.w;
        }
        float4 vv = *(const float4*)&Vbase[(size_t)(j0 + vr) * DD + vc];
        *(float4*)&Vs[vr][vc] = vv;
        __syncthreads();
#pragma unroll
        for (int j = 0; j < 16; j++) {
            float4 v = *(const float4*)&Vs[j][tx * 4];
#pragma unroll
            for (int i = 0; i < 8; i++) {
                float a = Ps[j][ty * 8 + i];
                acc[i][0] += a * v.x;
                acc[i][1] += a * v.y;
                acc[i][2] += a * v.z;
                acc[i][3] += a * v.w;
            }
        }
        __syncthreads();
    }

#pragma unroll
    for (int i = 0; i < 8; i++) {
        float* op = g_O + ((size_t)b * NN + n0 + ty * 8 + i) * DD + h * HD + tx * 4;
        *(float4*)op = make_float4(acc[i][0], acc[i][1], acc[i][2], acc[i][3]);
    }
}

// ---------------------------------------------------------------------------
// wmean[b,n,j] = mean_h P[b,h,n,j]; 0 above the causal diagonal. float4.
// ---------------------------------------------------------------------------
__global__ __launch_bounds__(256) void attn_wmean(const int* __restrict__ flag,
                                                  float* __restrict__ wout)
{
    const int blk = blockIdx.x;            // b*NN + n
    const int b = blk >> 11, n = blk & (NN - 1);
    const int causal = (flag[0] != 0);

    const float* base = g_S + ((size_t)(b * HH) * NN + n) * MM;
    float* orow = wout + (size_t)blk * MM;

    for (int j4 = threadIdx.x * 4; j4 < MM; j4 += 1024) {
        float4 a = make_float4(0.f, 0.f, 0.f, 0.f);
        if (!causal || j4 <= n) {
#pragma unroll
            for (int h = 0; h < HH; h++) {
                float4 v = *(const float4*)&base[(size_t)h * NN * MM + j4];
                a.x += v.x; a.y += v.y; a.z += v.z; a.w += v.w;
            }
            a.x *= (1.0f / HH); a.y *= (1.0f / HH);
            a.z *= (1.0f / HH); a.w *= (1.0f / HH);
            if (causal) {
                if (j4 + 1 > n) a.y = 0.f;
                if (j4 + 2 > n) a.z = 0.f;
                if (j4 + 3 > n) a.w = 0.f;
            }
        }
        *(float4*)&orow[j4] = a;
    }
}

// ---------------------------------------------------------------------------
// Launch
// ---------------------------------------------------------------------------
extern "C" void kernel_launch(void* const* d_in, const int* in_sizes, int n_in,
                              void* d_out, int out_size)
{
    const float* query = (const float*)d_in[0];
    const float* key   = (const float*)d_in[1];
    const float* value = (const float*)d_in[2];
    const int*   kpl   = (const int*)d_in[3];
    const int*   flag  = (const int*)d_in[4];
    const float* wq_w  = (const float*)d_in[5];
    const float* wq_b  = (const float*)d_in[6];
    const float* wk_w  = (const float*)d_in[7];
    const float* wk_b  = (const float*)d_in[8];
    const float* wv_w  = (const float*)d_in[9];
    const float* wv_b  = (const float*)d_in[10];
    const float* wo_w  = (const float*)d_in[11];
    const float* wo_b  = (const float*)d_in[12];
    float* out = (float*)d_out;

    float *Qp, *Kp, *Vp, *Op;
    cudaGetSymbolAddress((void**)&Qp, g_Q);
    cudaGetSymbolAddress((void**)&Kp, g_K);
    cudaGetSymbolAddress((void**)&Vp, g_V);
    cudaGetSymbolAddress((void**)&Op, g_O);

    const dim3 gProj(32, 8);   // 4096/128 x 1024/128

    proj_mma<<<gProj, 256>>>(query, wq_w, wq_b, Qp, nullptr);
    proj_mma<<<gProj, 256>>>(key,   wk_w, wk_b, Kp, kpl);
    proj_mma<<<gProj, 256>>>(value, wv_w, wv_b, Vp, nullptr);

    scores_mma  <<<dim3(16, 16, 32), 256>>>(flag);
    attn_softmax<<<BB * HH * NN, 256>>>(flag);
    attn_ov     <<<dim3(16, 32), 256>>>(flag);

    proj_mma<<<gProj, 256>>>(Op, wo_w, wo_b, out, nullptr);

    const long long need = (long long)BB * NN * DD + (long long)BB * NN * MM;
    if ((long long)out_size >= need)
        attn_wmean<<<BB * NN, 256>>>(flag, out + (size_t)BB * NN * DD);
}